// round 8
// baseline (speedup 1.0000x reference)
#include <cuda_runtime.h>
#include <cuda_fp16.h>

// ---------------------------------------------------------------------------
// RegularGridInterpolator: trilinear interp of N points into [32,128,128,128].
// Points in [0,1) -> only tick indices [63,127] reachable per dim.
//   1) pre: one kernel, two block ranges:
//      a) xpose blocks: hot region -> z-pair-duplicated channel-interleaved
//         fp16 layout. entry(ii,jj,kk) = 128B = half2(c@kk, c@kk+1), c=0..31.
//      b) prep blocks: per point, base entry index (*8) + 4 z-folded half2
//         corner weights. Runs concurrently with (a) on the same grid.
//   2) gather: 8 lanes per point-PAIR. Per point each xy-corner is EXACTLY
//      one aligned 128B line. No shuffles, no prep math: 2 broadcast prep
//      loads + 8 corner LDG.128 + HFMA2 + fp32 horizontal add + float4 store.
// ---------------------------------------------------------------------------

#define NPTS_MAX 2000000
#define XBLOCKS  (65 * 65)

// 65*65*64 entries * 8 uint4 = 34.6 MB
__device__ uint4 g_gt[65 * 65 * 64 * 8];
__device__ int   g_base[NPTS_MAX];     // entry index * 8 (uint4 units)
__device__ uint4 g_w[NPTS_MAX];        // 4 x half2 corner weights (z-folded)

// ---------------- prep math --------------------------------------------------
// ticks[i] = i/64 - 1 exactly in fp32. x in [0,1): s = x*64 is EXACT
// (power-of-two scale), so searchsorted(side='left') == 64 + ceil(s) exactly.
__device__ __forceinline__ void dim_prep(float x, int& il, float& f) {
    float s = x * 64.0f;                       // exact
    int ir = 64 + __float2int_ru(s);
    ir = min(max(ir, 64), 127);                // matches reference clip
    il = ir - 1;
    float tl = (float)(il - 64) * 0.015625f;   // exact tick value
    float tr = tl + 0.015625f;                 // exact (multiples of 2^-6 < 1)
    float dl = fmaxf(x - tl, 0.0f);
    float dr = fmaxf(tr - x, 0.0f);
    f = __fdividef(dl, dl + dr);               // weight of RIGHT corner (dl>0)
}

// ---------------- 1) fused xpose + prep --------------------------------------
__global__ void pre_kernel(const float4* __restrict__ g4, __half2* __restrict__ gt2,
                           const float* __restrict__ pts,
                           int* __restrict__ bases, uint4* __restrict__ wts, int n) {
    if (blockIdx.x < XBLOCKS) {
        // ---- xpose: read k in [60,128) (float4 q = 15..31), write z-pairs
        __shared__ float tile[32 * 65];        // stride 65 (odd -> conflict-free)
        int ii = blockIdx.x / 65;
        int jj = blockIdx.x - ii * 65;
        int i = ii + 63, j = jj + 63;
        for (int idx = threadIdx.x; idx < 544; idx += 256) {
            int c = idx / 17;
            int q = 15 + (idx - c * 17);
            float4 v = g4[(((size_t)c * 128 + i) * 128 + j) * 32 + q];
            int kk = q * 4 - 63;               // k - 63
            if (kk >= 0)                    tile[c * 65 + kk]     = v.x;
            if (kk + 1 >= 0)                tile[c * 65 + kk + 1] = v.y;
            if (kk + 2 >= 0 && kk + 2 < 65) tile[c * 65 + kk + 2] = v.z;
            if (kk + 3 >= 0 && kk + 3 < 65) tile[c * 65 + kk + 3] = v.w;
        }
        __syncthreads();
        __half2* dst = gt2 + (size_t)(ii * 65 + jj) * 64 * 32;
        for (int idx = threadIdx.x; idx < 64 * 32; idx += 256) {
            int kk = idx >> 5;
            int c  = idx & 31;
            dst[idx] = __floats2half2_rn(tile[c * 65 + kk], tile[c * 65 + kk + 1]);
        }
    } else {
        // ---- prep: one thread per point
        int pid = (blockIdx.x - XBLOCKS) * 256 + threadIdx.x;
        if (pid >= n) return;
        float x = __ldg(pts + pid * 3 + 0);
        float y = __ldg(pts + pid * 3 + 1);
        float z = __ldg(pts + pid * 3 + 2);
        int ix, iy, iz; float fx, fy, fz;
        dim_prep(x, ix, fx);
        dim_prep(y, iy, fy);
        dim_prep(z, iz, fz);
        int base = ((ix - 63) * 65 + (iy - 63)) * 64 + (iz - 63);
        bases[pid] = base * 8;                 // uint4 units
        float gx = 1.0f - fx, gy = 1.0f - fy, gz = 1.0f - fz;
        float c0 = gx * gy, c1 = gx * fy, c2 = fx * gy, c3 = fx * fy;
        __half2 w0 = __floats2half2_rn(c0 * gz, c0 * fz);
        __half2 w1 = __floats2half2_rn(c1 * gz, c1 * fz);
        __half2 w2 = __floats2half2_rn(c2 * gz, c2 * fz);
        __half2 w3 = __floats2half2_rn(c3 * gz, c3 * fz);
        uint4 w;
        w.x = *(const unsigned*)&w0; w.y = *(const unsigned*)&w1;
        w.z = *(const unsigned*)&w2; w.w = *(const unsigned*)&w3;
        wts[pid] = w;
    }
}

// corner offsets in uint4 units (entry = 128B = 8 uint4)
#define OFF_Y (64 * 8)
#define OFF_X (65 * 64 * 8)

// ---------------- 2) gather --------------------------------------------------
__global__ void __launch_bounds__(256) gather_kernel(
        const int* __restrict__ bases, const uint4* __restrict__ wts,
        const uint4* __restrict__ gt, float4* __restrict__ out, int n) {
    int t = blockIdx.x * blockDim.x + threadIdx.x;
    int g = t >> 3;                            // group: 8 lanes, 2 points
    int sub = t & 7;
    int pA = g * 2, pB = pA + 1;
    bool vA = pA < n, vB = pB < n;
    int pAc = vA ? pA : n - 1;
    int pBc = vB ? pB : n - 1;

    int baseA = __ldg(bases + pAc);            // broadcast within group
    int baseB = __ldg(bases + pBc);
    uint4 wAp = __ldg(wts + pAc);
    uint4 wBp = __ldg(wts + pBc);

    const uint4* gpA = gt + baseA + sub;       // 8 lanes cover one 128B entry
    const uint4* gpB = gt + baseB + sub;

    // 8 independent corner loads in flight (MLP = 8)
    uint4 vAv[4], vBv[4];
    {
        const int offs[4] = { 0, OFF_Y, OFF_X, OFF_X + OFF_Y };
#pragma unroll
        for (int c = 0; c < 4; c++) vAv[c] = __ldg(gpA + offs[c]);
#pragma unroll
        for (int c = 0; c < 4; c++) vBv[c] = __ldg(gpB + offs[c]);
    }

    const __half2* wA = (const __half2*)&wAp;
    const __half2* wB = (const __half2*)&wBp;

    __half2 zero = __float2half2_rn(0.0f);
    __half2 aA0 = zero, aA1 = zero, aA2 = zero, aA3 = zero;
    __half2 aB0 = zero, aB1 = zero, aB2 = zero, aB3 = zero;
#pragma unroll
    for (int c = 0; c < 4; c++) {
        aA0 = __hfma2(wA[c], *(const __half2*)&vAv[c].x, aA0);
        aA1 = __hfma2(wA[c], *(const __half2*)&vAv[c].y, aA1);
        aA2 = __hfma2(wA[c], *(const __half2*)&vAv[c].z, aA2);
        aA3 = __hfma2(wA[c], *(const __half2*)&vAv[c].w, aA3);
        aB0 = __hfma2(wB[c], *(const __half2*)&vBv[c].x, aB0);
        aB1 = __hfma2(wB[c], *(const __half2*)&vBv[c].y, aB1);
        aB2 = __hfma2(wB[c], *(const __half2*)&vBv[c].z, aB2);
        aB3 = __hfma2(wB[c], *(const __half2*)&vBv[c].w, aB3);
    }

    // horizontal z-merge in fp32; lane sub owns channels [4sub, 4sub+4)
    if (vA) {
        out[(size_t)pA * 8 + sub] = make_float4(
            __low2float(aA0) + __high2float(aA0),
            __low2float(aA1) + __high2float(aA1),
            __low2float(aA2) + __high2float(aA2),
            __low2float(aA3) + __high2float(aA3));
    }
    if (vB) {
        out[(size_t)pB * 8 + sub] = make_float4(
            __low2float(aB0) + __high2float(aB0),
            __low2float(aB1) + __high2float(aB1),
            __low2float(aB2) + __high2float(aB2),
            __low2float(aB3) + __high2float(aB3));
    }
}

// ---------------------------------------------------------------------------
extern "C" void kernel_launch(void* const* d_in, const int* in_sizes, int n_in,
                              void* d_out, int out_size) {
    const float* pts  = (const float*)d_in[0];   // [N,3]
    const float* grid = (const float*)d_in[1];   // [32,128,128,128]
    float* out = (float*)d_out;                  // [N,32]
    int n = in_sizes[0] / 3;

    uint4* gt;    cudaGetSymbolAddress((void**)&gt,    g_gt);
    int*   bases; cudaGetSymbolAddress((void**)&bases, g_base);
    uint4* wts;   cudaGetSymbolAddress((void**)&wts,   g_w);

    int prep_blocks = (n + 255) / 256;
    pre_kernel<<<XBLOCKS + prep_blocks, 256>>>((const float4*)grid, (__half2*)gt,
                                               pts, bases, wts, n);
    long long groups = (n + 1) / 2;              // 2 points per 8-lane group
    long long threads = groups * 8;
    int blocks = (int)((threads + 255) / 256);
    gather_kernel<<<blocks, 256>>>(bases, wts, gt, (float4*)out, n);
}

// round 9
// speedup vs baseline: 1.1797x; 1.1797x over previous
#include <cuda_runtime.h>
#include <cuda_fp16.h>

// ---------------------------------------------------------------------------
// RegularGridInterpolator: trilinear interp of N points into [32,128,128,128].
// Points in [0,1) -> only tick indices [63,127] reachable per dim.
//   1) xpose: hot region -> z-pair-duplicated channel-interleaved fp16 layout:
//      entry(ii,jj,kk) = 128B = half2(c@kk, c@kk+1), c=0..31. [65][65][64].
//   2) gather: 8 lanes per point-PAIR (MLP=8). Per point each xy-corner is
//      EXACTLY one aligned 128B line. Prep on lanes 0-2/4-6, shfl broadcast.
//      Output via __stcs streaming stores -> keep grid resident in L2.
// ---------------------------------------------------------------------------

// 65*65*64 entries * 8 uint4 = 34.6 MB
__device__ uint4 g_gt[65 * 65 * 64 * 8];

// ---------------- 1) layout transform + fp16 convert ------------------------
__global__ void xpose_kernel(const float4* __restrict__ g4, __half2* __restrict__ gt2) {
    __shared__ float tile[32 * 65];            // stride 65 (odd -> conflict-free)
    int ii = blockIdx.x / 65;
    int jj = blockIdx.x - ii * 65;
    int i = ii + 63, j = jj + 63;
    // 32 ch x 17 float4 = 544 loads covering k in [60,127]
    for (int idx = threadIdx.x; idx < 544; idx += 256) {
        int c = idx / 17;
        int q = 15 + (idx - c * 17);
        float4 v = g4[(((size_t)c * 128 + i) * 128 + j) * 32 + q];
        int kk = q * 4 - 63;                   // k - 63
        if (kk >= 0)                    tile[c * 65 + kk]     = v.x;
        if (kk + 1 >= 0)                tile[c * 65 + kk + 1] = v.y;
        if (kk + 2 >= 0 && kk + 2 < 65) tile[c * 65 + kk + 2] = v.z;
        if (kk + 3 >= 0 && kk + 3 < 65) tile[c * 65 + kk + 3] = v.w;
    }
    __syncthreads();
    __half2* dst = gt2 + (size_t)(ii * 65 + jj) * 64 * 32;
    for (int idx = threadIdx.x; idx < 64 * 32; idx += 256) {
        int kk = idx >> 5;
        int c  = idx & 31;
        dst[idx] = __floats2half2_rn(tile[c * 65 + kk], tile[c * 65 + kk + 1]);
    }
}

// ---------------- 2) fused prep + gather -------------------------------------
// ticks[i] = i/64 - 1 exactly in fp32. x in [0,1): s = x*64 is EXACT
// (power-of-two scale), so searchsorted(side='left') == 64 + ceil(s) exactly.
__device__ __forceinline__ void dim_prep(float x, int& il, float& f) {
    float s = x * 64.0f;                       // exact
    int ir = 64 + __float2int_ru(s);
    ir = min(max(ir, 64), 127);                // matches reference clip
    il = ir - 1;
    float tl = (float)(il - 64) * 0.015625f;   // exact tick value
    float tr = tl + 0.015625f;                 // exact (multiples of 2^-6 < 1)
    float dl = fmaxf(x - tl, 0.0f);
    float dr = fmaxf(tr - x, 0.0f);
    f = __fdividef(dl, dl + dr);               // weight of RIGHT corner (dl>0)
}

// corner offsets in uint4 units (entry = 128B = 8 uint4)
#define OFF_Y (64 * 8)
#define OFF_X (65 * 64 * 8)

__global__ void __launch_bounds__(256) gather_kernel(
        const float* __restrict__ pts, const uint4* __restrict__ gt,
        float4* __restrict__ out, int n) {
    const unsigned FULL = 0xFFFFFFFFu;
    int t = blockIdx.x * blockDim.x + threadIdx.x;
    int g = t >> 3;                            // group: 8 lanes, 2 points
    int sub = t & 7;
    int pA = g * 2, pB = pA + 1;
    bool vA = pA < n, vB = pB < n;
    int pAc = vA ? pA : n - 1;
    int pBc = vB ? pB : n - 1;

    // lanes 0/1/2 prep point A dims, lanes 4/5/6 prep point B dims
    int psel = (sub & 4) ? pBc : pAc;
    int cdim = min(sub & 3, 2);
    float coord = __ldg(pts + psel * 3 + cdim);
    int ic; float fc;
    dim_prep(coord, ic, fc);

    int   ixA = __shfl_sync(FULL, ic, 0, 8), ixB = __shfl_sync(FULL, ic, 4, 8);
    int   iyA = __shfl_sync(FULL, ic, 1, 8), iyB = __shfl_sync(FULL, ic, 5, 8);
    int   izA = __shfl_sync(FULL, ic, 2, 8), izB = __shfl_sync(FULL, ic, 6, 8);
    float fxA = __shfl_sync(FULL, fc, 0, 8), fxB = __shfl_sync(FULL, fc, 4, 8);
    float fyA = __shfl_sync(FULL, fc, 1, 8), fyB = __shfl_sync(FULL, fc, 5, 8);
    float fzA = __shfl_sync(FULL, fc, 2, 8), fzB = __shfl_sync(FULL, fc, 6, 8);

    int baseA = ((ixA - 63) * 65 + (iyA - 63)) * 64 + (izA - 63);
    int baseB = ((ixB - 63) * 65 + (iyB - 63)) * 64 + (izB - 63);
    const uint4* gpA = gt + baseA * 8 + sub;   // 8 lanes cover one 128B entry
    const uint4* gpB = gt + baseB * 8 + sub;

    // issue all 8 independent corner loads up front (MLP = 8)
    uint4 vAv[4], vBv[4];
    {
        const int offs[4] = { 0, OFF_Y, OFF_X, OFF_X + OFF_Y };
#pragma unroll
        for (int c = 0; c < 4; c++) vAv[c] = __ldg(gpA + offs[c]);
#pragma unroll
        for (int c = 0; c < 4; c++) vBv[c] = __ldg(gpB + offs[c]);
    }

    float gxA = 1.0f - fxA, gyA = 1.0f - fyA, gzA = 1.0f - fzA;
    float gxB = 1.0f - fxB, gyB = 1.0f - fyB, gzB = 1.0f - fzB;
    // per-corner z-pair weights: half2(wc*gz, wc*fz)
    __half2 wA[4], wB[4];
    {
        float c0 = gxA * gyA, c1 = gxA * fyA, c2 = fxA * gyA, c3 = fxA * fyA;
        wA[0] = __floats2half2_rn(c0 * gzA, c0 * fzA);
        wA[1] = __floats2half2_rn(c1 * gzA, c1 * fzA);
        wA[2] = __floats2half2_rn(c2 * gzA, c2 * fzA);
        wA[3] = __floats2half2_rn(c3 * gzA, c3 * fzA);
        float d0 = gxB * gyB, d1 = gxB * fyB, d2 = fxB * gyB, d3 = fxB * fyB;
        wB[0] = __floats2half2_rn(d0 * gzB, d0 * fzB);
        wB[1] = __floats2half2_rn(d1 * gzB, d1 * fzB);
        wB[2] = __floats2half2_rn(d2 * gzB, d2 * fzB);
        wB[3] = __floats2half2_rn(d3 * gzB, d3 * fzB);
    }

    __half2 zero = __float2half2_rn(0.0f);
    __half2 aA0 = zero, aA1 = zero, aA2 = zero, aA3 = zero;
    __half2 aB0 = zero, aB1 = zero, aB2 = zero, aB3 = zero;
#pragma unroll
    for (int c = 0; c < 4; c++) {
        aA0 = __hfma2(wA[c], *(const __half2*)&vAv[c].x, aA0);
        aA1 = __hfma2(wA[c], *(const __half2*)&vAv[c].y, aA1);
        aA2 = __hfma2(wA[c], *(const __half2*)&vAv[c].z, aA2);
        aA3 = __hfma2(wA[c], *(const __half2*)&vAv[c].w, aA3);
        aB0 = __hfma2(wB[c], *(const __half2*)&vBv[c].x, aB0);
        aB1 = __hfma2(wB[c], *(const __half2*)&vBv[c].y, aB1);
        aB2 = __hfma2(wB[c], *(const __half2*)&vBv[c].z, aB2);
        aB3 = __hfma2(wB[c], *(const __half2*)&vBv[c].w, aB3);
    }

    // horizontal z-merge in fp32; lane sub owns channels [4sub, 4sub+4)
    // Streaming stores: keep the 34.6 MB grid resident in L2.
    if (vA) {
        __stcs(out + (size_t)pA * 8 + sub, make_float4(
            __low2float(aA0) + __high2float(aA0),
            __low2float(aA1) + __high2float(aA1),
            __low2float(aA2) + __high2float(aA2),
            __low2float(aA3) + __high2float(aA3)));
    }
    if (vB) {
        __stcs(out + (size_t)pB * 8 + sub, make_float4(
            __low2float(aB0) + __high2float(aB0),
            __low2float(aB1) + __high2float(aB1),
            __low2float(aB2) + __high2float(aB2),
            __low2float(aB3) + __high2float(aB3)));
    }
}

// ---------------------------------------------------------------------------
extern "C" void kernel_launch(void* const* d_in, const int* in_sizes, int n_in,
                              void* d_out, int out_size) {
    const float* pts  = (const float*)d_in[0];   // [N,3]
    const float* grid = (const float*)d_in[1];   // [32,128,128,128]
    float* out = (float*)d_out;                  // [N,32]
    int n = in_sizes[0] / 3;

    uint4* gt; cudaGetSymbolAddress((void**)&gt, g_gt);

    xpose_kernel<<<65 * 65, 256>>>((const float4*)grid, (__half2*)gt);
    long long groups = (n + 1) / 2;              // 2 points per 8-lane group
    long long threads = groups * 8;
    int blocks = (int)((threads + 255) / 256);
    gather_kernel<<<blocks, 256>>>(pts, gt, (float4*)out, n);
}